// round 10
// baseline (speedup 1.0000x reference)
#include <cuda_runtime.h>
#include <cuda_bf16.h>
#include <math.h>
#include <stdint.h>

// Problem constants
#define BB 8
#define MM 256
#define EE 128
#define KK 16
#define HH 1024
#define AA 256
#define RR 1024
#define RMS 512
#define BE (BB*EE)          // 1024
#define BM_TOT (BB*MM)      // 2048 unique mentions
#define ZW (HH + RMS)       // 1536

// Scratch (device globals; allocation is forbidden)
__device__ float g_P[BM_TOT * 2 * AA];  // [2048, 512]: cols 0..255 = Pv, 256..511 = Pu
__device__ float g_L[BM_TOT];           // per-mention logits
__device__ float g_attn[BE * KK];
__device__ float g_E[BE * HH];          // entity reprs
__device__ float g_RMt[RMS * RR];       // RM^T [512,1024]
__device__ float g_C[RMS * RMS];        // RM^T RM (Gram, symmetric) [512,512]
__device__ float g_r[RMS];              // colsum(RM) [512]
__device__ float g_Teff[HH * RMS];      // Wr·C + br·r^T  [1024,512]
__device__ float g_G[HH * HH];          // Wo1 + Wo2·Teff^T [1024,1024]

__device__ __forceinline__ uint32_t smem_to_u32(const void* p) {
    uint32_t a;
    asm("{ .reg .u64 t; cvta.to.shared.u64 t, %1; cvt.u32.u64 %0, t; }"
        : "=r"(a) : "l"(p));
    return a;
}

// Split one float4 into packed bf16 hi/lo (uint2 each)
__device__ __forceinline__ void split4(float4 v, uint2& hi, uint2& lo) {
    __nv_bfloat16 hx = __float2bfloat16(v.x);
    __nv_bfloat16 hy = __float2bfloat16(v.y);
    __nv_bfloat16 hz = __float2bfloat16(v.z);
    __nv_bfloat16 hw = __float2bfloat16(v.w);
    __nv_bfloat16 lx = __float2bfloat16(v.x - __bfloat162float(hx));
    __nv_bfloat16 ly = __float2bfloat16(v.y - __bfloat162float(hy));
    __nv_bfloat16 lz = __float2bfloat16(v.z - __bfloat162float(hz));
    __nv_bfloat16 lw = __float2bfloat16(v.w - __bfloat162float(hw));
    hi.x = (uint32_t)__bfloat16_as_ushort(hx) | ((uint32_t)__bfloat16_as_ushort(hy) << 16);
    hi.y = (uint32_t)__bfloat16_as_ushort(hz) | ((uint32_t)__bfloat16_as_ushort(hw) << 16);
    lo.x = (uint32_t)__bfloat16_as_ushort(lx) | ((uint32_t)__bfloat16_as_ushort(ly) << 16);
    lo.y = (uint32_t)__bfloat16_as_ushort(lz) | ((uint32_t)__bfloat16_as_ushort(lw) << 16);
}

// ---------------------------------------------------------------------------
// bf16x3-split HMMA GEMM (mma.sync, sm_80+ path — works on plain sm_103):
//   C[M,N] = A[M,K]·B[N,K]^T (+ epilogue), fp32 in/out.
// 128x128 tile, 256 threads (8 warps, 2x4), warp tile 64x32 via m16n8k16.
// MODE: 0=none, 1=col bias bias[n], 2=add Cadd, 4=bias[m]*bias2[n]
// ---------------------------------------------------------------------------
#define TM 128
#define TN 128
#define TKC 32
#define KPAD 40   // bf16 elements per smem row (80B stride, ldmatrix conflict-free)

template<int MODE>
__global__ void __launch_bounds__(256)
mmagemm(const float* __restrict__ A, const float* __restrict__ B,
        const float* __restrict__ bias, const float* __restrict__ bias2,
        const float* __restrict__ Cadd, float* __restrict__ C,
        int lda, int ldb, int ldc, int ldadd, int Kdim)
{
    __shared__ __nv_bfloat16 sAhi[TM * KPAD];
    __shared__ __nv_bfloat16 sAlo[TM * KPAD];
    __shared__ __nv_bfloat16 sBhi[TN * KPAD];
    __shared__ __nv_bfloat16 sBlo[TN * KPAD];

    const int tid  = threadIdx.x;
    const int lane = tid & 31;
    const int wid  = tid >> 5;
    const int wm   = wid & 1;    // warp M block (0..1) of 64 rows
    const int wn   = wid >> 1;   // warp N block (0..3) of 32 cols
    const int bx = blockIdx.x, by = blockIdx.y;

    const uint32_t uAhi = smem_to_u32(sAhi);
    const uint32_t uAlo = smem_to_u32(sAlo);
    const uint32_t uBhi = smem_to_u32(sBhi);
    const uint32_t uBlo = smem_to_u32(sBlo);

    float acc[4][4][4];
#pragma unroll
    for (int i = 0; i < 4; i++)
#pragma unroll
        for (int j = 0; j < 4; j++)
#pragma unroll
            for (int q = 0; q < 4; q++) acc[i][j][q] = 0.f;

    const float* Abase = A + (size_t)(by * TM) * lda;
    const float* Bbase = B + (size_t)(bx * TN) * ldb;

    // staging map: thread -> (row, 4-col group); 8 threads cover one 32-col row
    const int srow = tid >> 3;        // 0..31 (row within pass)
    const int scol = (tid & 7) * 4;   // 0,4,...,28

    // ldmatrix lane addressing (element offsets within a tile row computed later)
    const int aRow = lane & 15;               // row within 16-row block
    const int aKh  = (lane >> 4) * 8;         // k half (0 or 8)
    const int bRow = lane & 7;                // n row within 8-row block
    const int bKh  = ((lane >> 3) & 1) * 8;   // k half

    for (int k0 = 0; k0 < Kdim; k0 += TKC) {
        // ---- stage + split (4 passes of 32 rows) ----
#pragma unroll
        for (int p = 0; p < 4; p++) {
            const int r = p * 32 + srow;
            float4 va = *(const float4*)(Abase + (size_t)r * lda + k0 + scol);
            float4 vb = *(const float4*)(Bbase + (size_t)r * ldb + k0 + scol);
            uint2 hi, lo;
            split4(va, hi, lo);
            *(uint2*)(sAhi + r * KPAD + scol) = hi;
            *(uint2*)(sAlo + r * KPAD + scol) = lo;
            split4(vb, hi, lo);
            *(uint2*)(sBhi + r * KPAD + scol) = hi;
            *(uint2*)(sBlo + r * KPAD + scol) = lo;
        }
        __syncthreads();

        // ---- 3 split terms: (Ahi,Bhi), (Ahi,Blo), (Alo,Bhi) ----
#pragma unroll
        for (int term = 0; term < 3; term++) {
            const uint32_t aB = (term == 2) ? uAlo : uAhi;
            const uint32_t bB = (term == 1) ? uBlo : uBhi;
#pragma unroll
            for (int ks = 0; ks < 2; ks++) {
                const int koff = ks * 16;
                // B fragments: 4 n8 tiles
                uint32_t bf[4][2];
#pragma unroll
                for (int j = 0; j < 4; j++) {
                    const int bn = wn * 32 + j * 8;
                    const uint32_t addr = bB +
                        (uint32_t)(((bn + bRow) * KPAD + koff + bKh) * 2);
                    asm volatile(
                        "ldmatrix.sync.aligned.m8n8.x2.shared.b16 {%0,%1}, [%2];"
                        : "=r"(bf[j][0]), "=r"(bf[j][1]) : "r"(addr));
                }
                // A fragments: 4 m16 tiles
                uint32_t af[4][4];
#pragma unroll
                for (int i = 0; i < 4; i++) {
                    const int bm = wm * 64 + i * 16;
                    const uint32_t addr = aB +
                        (uint32_t)(((bm + aRow) * KPAD + koff + aKh) * 2);
                    asm volatile(
                        "ldmatrix.sync.aligned.m8n8.x4.shared.b16 {%0,%1,%2,%3}, [%4];"
                        : "=r"(af[i][0]), "=r"(af[i][1]),
                          "=r"(af[i][2]), "=r"(af[i][3]) : "r"(addr));
                }
#pragma unroll
                for (int i = 0; i < 4; i++)
#pragma unroll
                    for (int j = 0; j < 4; j++) {
                        asm volatile(
                            "mma.sync.aligned.m16n8k16.row.col.f32.bf16.bf16.f32 "
                            "{%0,%1,%2,%3}, {%4,%5,%6,%7}, {%8,%9}, {%0,%1,%2,%3};"
                            : "+f"(acc[i][j][0]), "+f"(acc[i][j][1]),
                              "+f"(acc[i][j][2]), "+f"(acc[i][j][3])
                            : "r"(af[i][0]), "r"(af[i][1]),
                              "r"(af[i][2]), "r"(af[i][3]),
                              "r"(bf[j][0]), "r"(bf[j][1]));
                    }
            }
        }
        __syncthreads();
    }

    // ---- epilogue ----
    const int mBase = by * TM + wm * 64;
    const int nBase = bx * TN + wn * 32;
    const int rOff = lane >> 2;          // 0..7
    const int cOff = (lane & 3) * 2;     // 0,2,4,6
#pragma unroll
    for (int i = 0; i < 4; i++) {
        const int r0 = mBase + i * 16 + rOff;
        const int r1 = r0 + 8;
        float rb0 = 0.f, rb1 = 0.f;
        if (MODE == 4) { rb0 = bias[r0]; rb1 = bias[r1]; }
#pragma unroll
        for (int j = 0; j < 4; j++) {
            const int cn = nBase + j * 8 + cOff;
            float2 v0 = make_float2(acc[i][j][0], acc[i][j][1]);
            float2 v1 = make_float2(acc[i][j][2], acc[i][j][3]);
            if (MODE == 1) {
                v0.x += bias[cn]; v0.y += bias[cn + 1];
                v1.x += bias[cn]; v1.y += bias[cn + 1];
            }
            if (MODE == 4) {
                v0.x += rb0 * bias2[cn]; v0.y += rb0 * bias2[cn + 1];
                v1.x += rb1 * bias2[cn]; v1.y += rb1 * bias2[cn + 1];
            }
            if (MODE == 2) {
                const float2 c0 = *(const float2*)(Cadd + (size_t)r0 * ldadd + cn);
                const float2 c1 = *(const float2*)(Cadd + (size_t)r1 * ldadd + cn);
                v0.x += c0.x; v0.y += c0.y;
                v1.x += c1.x; v1.y += c1.y;
            }
            *(float2*)(C + (size_t)r0 * ldc + cn) = v0;
            *(float2*)(C + (size_t)r1 * ldc + cn) = v1;
        }
    }
}

// ---------------------------------------------------------------------------
// Per-mention MIL logit: L[row] = Wa . (tanh(Pv+bv) * sigmoid(Pu+bu)) + ba
// ---------------------------------------------------------------------------
__global__ void __launch_bounds__(256)
mil_logits(const float* __restrict__ P, const float* __restrict__ bv,
           const float* __restrict__ bu, const float* __restrict__ Wa,
           const float* __restrict__ ba, float* __restrict__ L)
{
    const int w = (blockIdx.x * 256 + threadIdx.x) >> 5;   // 0..2047
    const int lane = threadIdx.x & 31;
    const float* p = P + (size_t)w * (2 * AA);
    float sum = 0.f;
#pragma unroll
    for (int j = 0; j < 8; j++) {
        int a = lane + j * 32;
        float v = tanhf(p[a] + bv[a]);
        float u = 1.f / (1.f + expf(-(p[AA + a] + bu[a])));
        sum += v * u * Wa[a];
    }
#pragma unroll
    for (int o = 16; o; o >>= 1) sum += __shfl_xor_sync(0xffffffffu, sum, o);
    if (lane == 0) L[w] = sum + ba[0];
}

// ---------------------------------------------------------------------------
// Gather per-mention logits, mask, softmax over K=16. One warp per (b,e).
// ---------------------------------------------------------------------------
__global__ void __launch_bounds__(256)
softmax16(const float* __restrict__ L, const int* __restrict__ ent,
          const int* __restrict__ mask, float* __restrict__ attn)
{
    const int w = (blockIdx.x * 256 + threadIdx.x) >> 5;   // be: 0..1023
    const int lane = threadIdx.x & 31;
    const int idx = w * KK + (lane & 15);
    float l = -1e30f;
    if (lane < KK) {
        int m = ent[idx];
        l = mask[idx] ? L[(w >> 7) * MM + m] : -1e25f;
    }
    float mx = l;
#pragma unroll
    for (int o = 8; o; o >>= 1) mx = fmaxf(mx, __shfl_xor_sync(0xffffffffu, mx, o));
    float e = expf(l - mx);
    float s = e;
#pragma unroll
    for (int o = 8; o; o >>= 1) s += __shfl_xor_sync(0xffffffffu, s, o);
    if (lane < KK) attn[idx] = e / s;
}

// ---------------------------------------------------------------------------
// Weighted pooling over K mentions -> entity reprs g_E [BE, H]
// ---------------------------------------------------------------------------
__global__ void __launch_bounds__(256)
pool_kernel(const float* __restrict__ attn, const int* __restrict__ ent,
            const float* __restrict__ mr, float* __restrict__ E)
{
    const int be = blockIdx.x;
    const int b = be >> 7;   // /E
    __shared__ float w[KK];
    __shared__ int rows[KK];
    if (threadIdx.x < KK) {
        w[threadIdx.x] = attn[be * KK + threadIdx.x];
        rows[threadIdx.x] = b * MM + ent[be * KK + threadIdx.x];
    }
    __syncthreads();
    for (int h = threadIdx.x; h < HH; h += 256) {
        float s = 0.f;
#pragma unroll
        for (int k = 0; k < KK; k++)
            s = fmaf(w[k], mr[(size_t)rows[k] * HH + h], s);
        E[(size_t)be * HH + h] = s;
    }
}

// ---------------------------------------------------------------------------
// Transpose relation_memory [R, RMS] -> RMt [RMS, R]
// ---------------------------------------------------------------------------
__global__ void __launch_bounds__(1024)
transpose_rm(const float* __restrict__ RM, float* __restrict__ RMt)
{
    __shared__ float t[32][33];
    const int r0 = blockIdx.y * 32;
    const int m0 = blockIdx.x * 32;
    t[threadIdx.y][threadIdx.x] = RM[(size_t)(r0 + threadIdx.y) * RMS + m0 + threadIdx.x];
    __syncthreads();
    RMt[(size_t)(m0 + threadIdx.y) * RR + r0 + threadIdx.x] = t[threadIdx.x][threadIdx.y];
}

// ---------------------------------------------------------------------------
// Column sums of RM: r[m] = sum_r RM[r, m]
// ---------------------------------------------------------------------------
__global__ void __launch_bounds__(128)
colsum_rm(const float* __restrict__ RM, float* __restrict__ r)
{
    const int m = blockIdx.x * 128 + threadIdx.x;   // 512 total
    float s = 0.f;
    for (int i = 0; i < RR; i++) s += RM[(size_t)i * RMS + m];
    r[m] = s;
}

// ---------------------------------------------------------------------------
extern "C" void kernel_launch(void* const* d_in, const int* in_sizes, int n_in,
                              void* d_out, int out_size)
{
    const float* mr   = (const float*)d_in[0];
    const int*   ent  = (const int*)  d_in[1];
    const int*   emask= (const int*)  d_in[2];
    const float* RM   = (const float*)d_in[3];
    const float* Wv   = (const float*)d_in[4];
    const float* bv   = (const float*)d_in[5];
    const float* Wu   = (const float*)d_in[6];
    const float* bu   = (const float*)d_in[7];
    const float* Wa   = (const float*)d_in[8];
    const float* ba   = (const float*)d_in[9];
    const float* Wr   = (const float*)d_in[10];
    const float* br   = (const float*)d_in[11];
    const float* Wo   = (const float*)d_in[12];
    const float* bo   = (const float*)d_in[13];
    float* out = (float*)d_out;

    float *P, *L, *attn, *E, *RMt, *Cg, *rv, *Teff, *G;
    cudaGetSymbolAddress((void**)&P,   g_P);
    cudaGetSymbolAddress((void**)&L,   g_L);
    cudaGetSymbolAddress((void**)&attn,g_attn);
    cudaGetSymbolAddress((void**)&E,   g_E);
    cudaGetSymbolAddress((void**)&RMt, g_RMt);
    cudaGetSymbolAddress((void**)&Cg,  g_C);
    cudaGetSymbolAddress((void**)&rv,  g_r);
    cudaGetSymbolAddress((void**)&Teff,g_Teff);
    cudaGetSymbolAddress((void**)&G,   g_G);

    // Side streams/events (host-side resources only; created once).
    static cudaStream_t s1 = nullptr, s2 = nullptr, s3 = nullptr;
    static cudaEvent_t eR = nullptr, e1 = nullptr, e2 = nullptr, e3 = nullptr;
    if (!s1) {
        cudaStreamCreateWithFlags(&s1, cudaStreamNonBlocking);
        cudaStreamCreateWithFlags(&s2, cudaStreamNonBlocking);
        cudaStreamCreateWithFlags(&s3, cudaStreamNonBlocking);
        cudaEventCreateWithFlags(&eR, cudaEventDisableTiming);
        cudaEventCreateWithFlags(&e1, cudaEventDisableTiming);
        cudaEventCreateWithFlags(&e2, cudaEventDisableTiming);
        cudaEventCreateWithFlags(&e3, cudaEventDisableTiming);
    }

    // fork
    cudaEventRecord(eR, 0);
    cudaStreamWaitEvent(s1, eR, 0);
    cudaStreamWaitEvent(s2, eR, 0);
    cudaStreamWaitEvent(s3, eR, 0);

    // --- branch A1 (s1): Pv = MR @ Wv^T -> P[:,0:256]  grid (2,16) ---
    mmagemm<0><<<dim3(AA / TN, BM_TOT / TM), 256, 0, s1>>>(
        mr, Wv, nullptr, nullptr, nullptr, P, HH, HH, 2 * AA, 0, HH);
    cudaEventRecord(e1, s1);

    // --- branch A2 (s2): Pu = MR @ Wu^T -> P[:,256:512]  grid (2,16) ---
    mmagemm<0><<<dim3(AA / TN, BM_TOT / TM), 256, 0, s2>>>(
        mr, Wu, nullptr, nullptr, nullptr, P + AA, HH, HH, 2 * AA, 0, HH);
    cudaEventRecord(e2, s2);

    // --- branch B (s3): effective output weight G via Gram matrix ---
    colsum_rm<<<RMS / 128, 128, 0, s3>>>(RM, rv);
    transpose_rm<<<dim3(RMS / 32, RR / 32), dim3(32, 32), 0, s3>>>(RM, RMt);
    // C = RMt @ RMt^T  [512,512,K=1024]  grid (4,4)
    mmagemm<0><<<dim3(RMS / TN, RMS / TM), 256, 0, s3>>>(
        RMt, RMt, nullptr, nullptr, nullptr, Cg, RR, RR, RMS, 0, RR);
    // Teff = Wr @ C (C symmetric) + br·r^T  [1024,512,K=512]  grid (4,8)
    mmagemm<4><<<dim3(RMS / TN, HH / TM), 256, 0, s3>>>(
        Wr, Cg, br, rv, nullptr, Teff, RMS, RMS, RMS, 0, RMS);
    // G = Wo2 @ Teff^T + Wo1  [1024,1024,K=512]  grid (8,8)
    mmagemm<2><<<dim3(HH / TN, HH / TM), 256, 0, s3>>>(
        Wo + HH, Teff, nullptr, nullptr, Wo, G, ZW, RMS, HH, ZW, RMS);
    cudaEventRecord(e3, s3);

    // --- default stream: attention chain after Pv,Pu ---
    cudaStreamWaitEvent(0, e1, 0);
    cudaStreamWaitEvent(0, e2, 0);
    mil_logits<<<BM_TOT / 8, 256>>>(P, bv, bu, Wa, ba, L);
    softmax16<<<BE / 8, 256>>>(L, ent, emask, attn);
    pool_kernel<<<BE, 256>>>(attn, ent, mr, E);

    // join with branch B, then final GEMM
    cudaStreamWaitEvent(0, e3, 0);
    // out = E @ G^T + bo  [1024,1024,K=1024]  grid (8,8)
    mmagemm<1><<<dim3(HH / TN, BE / TM), 256>>>(
        E, G, bo, nullptr, nullptr, out, HH, HH, HH, 0, HH);

    (void)in_sizes; (void)n_in; (void)out_size;
}

// round 12
// speedup vs baseline: 1.3708x; 1.3708x over previous
#include <cuda_runtime.h>
#include <cuda_bf16.h>
#include <math.h>
#include <stdint.h>

// Problem constants
#define BB 8
#define MM 256
#define EE 128
#define KK 16
#define HH 1024
#define AA 256
#define RR 1024
#define RMS 512
#define BE (BB*EE)          // 1024
#define BM_TOT (BB*MM)      // 2048 unique mentions
#define ZW (HH + RMS)       // 1536

// Scratch (device globals; allocation is forbidden)
__device__ float g_P[BM_TOT * 2 * AA];  // [2048, 512]: cols 0..255 = Pv, 256..511 = Pu
__device__ float g_L[BM_TOT];           // per-mention logits
__device__ float g_attn[BE * KK];
__device__ float g_E[BE * HH];          // entity reprs
__device__ float g_RMt[RMS * RR];       // RM^T [512,1024]
__device__ float g_C[RMS * RMS];        // RM^T RM (Gram, symmetric) [512,512]
__device__ float g_r[RMS];              // colsum(RM) [512]
__device__ float g_Teff[HH * RMS];      // Wr·C + br·r^T  [1024,512]
__device__ float g_G[HH * HH];          // Wo1 + Wo2·Teff^T [1024,1024]

__device__ __forceinline__ uint32_t smem_to_u32(const void* p) {
    uint32_t a;
    asm("{ .reg .u64 t; cvta.to.shared.u64 t, %1; cvt.u32.u64 %0, t; }"
        : "=r"(a) : "l"(p));
    return a;
}

// Split one float4 into packed bf16 hi/lo (uint2 each)
__device__ __forceinline__ void split4(float4 v, uint2& hi, uint2& lo) {
    __nv_bfloat16 hx = __float2bfloat16(v.x);
    __nv_bfloat16 hy = __float2bfloat16(v.y);
    __nv_bfloat16 hz = __float2bfloat16(v.z);
    __nv_bfloat16 hw = __float2bfloat16(v.w);
    __nv_bfloat16 lx = __float2bfloat16(v.x - __bfloat162float(hx));
    __nv_bfloat16 ly = __float2bfloat16(v.y - __bfloat162float(hy));
    __nv_bfloat16 lz = __float2bfloat16(v.z - __bfloat162float(hz));
    __nv_bfloat16 lw = __float2bfloat16(v.w - __bfloat162float(hw));
    hi.x = (uint32_t)__bfloat16_as_ushort(hx) | ((uint32_t)__bfloat16_as_ushort(hy) << 16);
    hi.y = (uint32_t)__bfloat16_as_ushort(hz) | ((uint32_t)__bfloat16_as_ushort(hw) << 16);
    lo.x = (uint32_t)__bfloat16_as_ushort(lx) | ((uint32_t)__bfloat16_as_ushort(ly) << 16);
    lo.y = (uint32_t)__bfloat16_as_ushort(lz) | ((uint32_t)__bfloat16_as_ushort(lw) << 16);
}

// ---------------------------------------------------------------------------
// bf16x3-split HMMA GEMM (mma.sync m16n8k16, sm_80+ path):
//   C[M,N] = A[M,K]·B[N,K]^T (+ epilogue), fp32 in/out.
// TM=128, TN=64, 256 threads (8 warps, 4 M-blocks x 2 N-blocks, warp 32x32).
// TKC=64, double-buffered smem: stage chunk i+1 overlaps MMA on chunk i.
// MODE: 0=none, 1=col bias bias[n], 2=add Cadd, 4=bias[m]*bias2[n]
// ---------------------------------------------------------------------------
#define TM 128
#define TN 64
#define TKC 64
#define KPAD 72                      // bf16 elems/row: 144B stride (16B-mult, ldm conflict-free)
#define OFF_AHI 0
#define OFF_ALO (TM * KPAD * 2)                  // 18432
#define OFF_BHI (OFF_ALO + TM * KPAD * 2)        // 36864
#define OFF_BLO (OFF_BHI + TN * KPAD * 2)        // 46080
#define SBUF    (OFF_BLO + TN * KPAD * 2)        // 55296 per buffer
#define MG_SMEM (2 * SBUF)                       // 110592 total

template<int MODE>
__global__ void __launch_bounds__(256)
mmagemm(const float* __restrict__ A, const float* __restrict__ B,
        const float* __restrict__ bias, const float* __restrict__ bias2,
        const float* __restrict__ Cadd, float* __restrict__ C,
        int lda, int ldb, int ldc, int ldadd, int Kdim)
{
    extern __shared__ char smem[];

    const int tid  = threadIdx.x;
    const int lane = tid & 31;
    const int wid  = tid >> 5;
    const int wm   = wid & 3;    // M block (0..3) of 32 rows
    const int wn   = wid >> 2;   // N block (0..1) of 32 cols
    const int bx = blockIdx.x, by = blockIdx.y;

    const uint32_t base_u = smem_to_u32(smem);

    float acc[2][4][4];
#pragma unroll
    for (int i = 0; i < 2; i++)
#pragma unroll
        for (int j = 0; j < 4; j++)
#pragma unroll
            for (int q = 0; q < 4; q++) acc[i][j][q] = 0.f;

    const float* Abase = A + (size_t)(by * TM) * lda;
    const float* Bbase = B + (size_t)(bx * TN) * ldb;

    // staging map: 16 threads per row (64 floats), 16 rows per pass
    const int srow = tid >> 4;        // 0..15
    const int scol = (tid & 15) * 4;  // 0,4,...,60

    // ldmatrix lane addressing
    const int aRow = lane & 15;               // row within 16-row block
    const int aKh  = (lane >> 4) * 8;         // k half (0 or 8)
    const int bRow = lane & 7;                // n row within 8-row block
    const int bKh  = ((lane >> 3) & 1) * 8;   // k half

    // stage one K-chunk into buffer `bsel`
    auto stage = [&](int bsel, int k0) {
        char* sb = smem + bsel * SBUF;
        __nv_bfloat16* pAhi = (__nv_bfloat16*)(sb + OFF_AHI);
        __nv_bfloat16* pAlo = (__nv_bfloat16*)(sb + OFF_ALO);
        __nv_bfloat16* pBhi = (__nv_bfloat16*)(sb + OFF_BHI);
        __nv_bfloat16* pBlo = (__nv_bfloat16*)(sb + OFF_BLO);
        uint2 hi, lo;
        // A: 128 rows in 8 passes of 16
#pragma unroll
        for (int p = 0; p < 8; p++) {
            const int r = p * 16 + srow;
            float4 v = *(const float4*)(Abase + (size_t)r * lda + k0 + scol);
            split4(v, hi, lo);
            *(uint2*)(pAhi + r * KPAD + scol) = hi;
            *(uint2*)(pAlo + r * KPAD + scol) = lo;
        }
        // B: 64 rows in 4 passes of 16
#pragma unroll
        for (int p = 0; p < 4; p++) {
            const int r = p * 16 + srow;
            float4 v = *(const float4*)(Bbase + (size_t)r * ldb + k0 + scol);
            split4(v, hi, lo);
            *(uint2*)(pBhi + r * KPAD + scol) = hi;
            *(uint2*)(pBlo + r * KPAD + scol) = lo;
        }
    };

    const int nch = Kdim / TKC;
    stage(0, 0);
    int buf = 0;
    for (int ch = 0; ch < nch; ch++) {
        __syncthreads();
        // stage next chunk into the other buffer (overlaps tensor work below)
        if (ch + 1 < nch) stage(buf ^ 1, (ch + 1) * TKC);

        const uint32_t bufu = base_u + buf * SBUF;
        // ---- 3 split terms: (Ahi,Bhi), (Ahi,Blo), (Alo,Bhi) ----
#pragma unroll
        for (int term = 0; term < 3; term++) {
            const uint32_t aB = bufu + ((term == 2) ? OFF_ALO : OFF_AHI);
            const uint32_t bB = bufu + ((term == 1) ? OFF_BLO : OFF_BHI);
#pragma unroll
            for (int ks = 0; ks < 4; ks++) {
                const int koff = ks * 16;
                // B fragments: 4 n8 tiles
                uint32_t bf[4][2];
#pragma unroll
                for (int j = 0; j < 4; j++) {
                    const int bn = wn * 32 + j * 8;
                    const uint32_t addr = bB +
                        (uint32_t)(((bn + bRow) * KPAD + koff + bKh) * 2);
                    asm volatile(
                        "ldmatrix.sync.aligned.m8n8.x2.shared.b16 {%0,%1}, [%2];"
                        : "=r"(bf[j][0]), "=r"(bf[j][1]) : "r"(addr));
                }
                // A fragments: 2 m16 tiles
                uint32_t af[2][4];
#pragma unroll
                for (int i = 0; i < 2; i++) {
                    const int bm = wm * 32 + i * 16;
                    const uint32_t addr = aB +
                        (uint32_t)(((bm + aRow) * KPAD + koff + aKh) * 2);
                    asm volatile(
                        "ldmatrix.sync.aligned.m8n8.x4.shared.b16 {%0,%1,%2,%3}, [%4];"
                        : "=r"(af[i][0]), "=r"(af[i][1]),
                          "=r"(af[i][2]), "=r"(af[i][3]) : "r"(addr));
                }
#pragma unroll
                for (int i = 0; i < 2; i++)
#pragma unroll
                    for (int j = 0; j < 4; j++) {
                        asm volatile(
                            "mma.sync.aligned.m16n8k16.row.col.f32.bf16.bf16.f32 "
                            "{%0,%1,%2,%3}, {%4,%5,%6,%7}, {%8,%9}, {%0,%1,%2,%3};"
                            : "+f"(acc[i][j][0]), "+f"(acc[i][j][1]),
                              "+f"(acc[i][j][2]), "+f"(acc[i][j][3])
                            : "r"(af[i][0]), "r"(af[i][1]),
                              "r"(af[i][2]), "r"(af[i][3]),
                              "r"(bf[j][0]), "r"(bf[j][1]));
                    }
            }
        }
        buf ^= 1;
    }

    // ---- epilogue ----
    const int mBase = by * TM + wm * 32;
    const int nBase = bx * TN + wn * 32;
    const int rOff = lane >> 2;          // 0..7
    const int cOff = (lane & 3) * 2;     // 0,2,4,6
#pragma unroll
    for (int i = 0; i < 2; i++) {
        const int r0 = mBase + i * 16 + rOff;
        const int r1 = r0 + 8;
        float rb0 = 0.f, rb1 = 0.f;
        if (MODE == 4) { rb0 = bias[r0]; rb1 = bias[r1]; }
#pragma unroll
        for (int j = 0; j < 4; j++) {
            const int cn = nBase + j * 8 + cOff;
            float2 v0 = make_float2(acc[i][j][0], acc[i][j][1]);
            float2 v1 = make_float2(acc[i][j][2], acc[i][j][3]);
            if (MODE == 1) {
                v0.x += bias[cn]; v0.y += bias[cn + 1];
                v1.x += bias[cn]; v1.y += bias[cn + 1];
            }
            if (MODE == 4) {
                v0.x += rb0 * bias2[cn]; v0.y += rb0 * bias2[cn + 1];
                v1.x += rb1 * bias2[cn]; v1.y += rb1 * bias2[cn + 1];
            }
            if (MODE == 2) {
                const float2 c0 = *(const float2*)(Cadd + (size_t)r0 * ldadd + cn);
                const float2 c1 = *(const float2*)(Cadd + (size_t)r1 * ldadd + cn);
                v0.x += c0.x; v0.y += c0.y;
                v1.x += c1.x; v1.y += c1.y;
            }
            *(float2*)(C + (size_t)r0 * ldc + cn) = v0;
            *(float2*)(C + (size_t)r1 * ldc + cn) = v1;
        }
    }
}

// ---------------------------------------------------------------------------
// Per-mention MIL logit: L[row] = Wa . (tanh(Pv+bv) * sigmoid(Pu+bu)) + ba
// ---------------------------------------------------------------------------
__global__ void __launch_bounds__(256)
mil_logits(const float* __restrict__ P, const float* __restrict__ bv,
           const float* __restrict__ bu, const float* __restrict__ Wa,
           const float* __restrict__ ba, float* __restrict__ L)
{
    const int w = (blockIdx.x * 256 + threadIdx.x) >> 5;   // 0..2047
    const int lane = threadIdx.x & 31;
    const float* p = P + (size_t)w * (2 * AA);
    float sum = 0.f;
#pragma unroll
    for (int j = 0; j < 8; j++) {
        int a = lane + j * 32;
        float v = tanhf(p[a] + bv[a]);
        float u = 1.f / (1.f + expf(-(p[AA + a] + bu[a])));
        sum += v * u * Wa[a];
    }
#pragma unroll
    for (int o = 16; o; o >>= 1) sum += __shfl_xor_sync(0xffffffffu, sum, o);
    if (lane == 0) L[w] = sum + ba[0];
}

// ---------------------------------------------------------------------------
// Gather per-mention logits, mask, softmax over K=16. One warp per (b,e).
// ---------------------------------------------------------------------------
__global__ void __launch_bounds__(256)
softmax16(const float* __restrict__ L, const int* __restrict__ ent,
          const int* __restrict__ mask, float* __restrict__ attn)
{
    const int w = (blockIdx.x * 256 + threadIdx.x) >> 5;   // be: 0..1023
    const int lane = threadIdx.x & 31;
    const int idx = w * KK + (lane & 15);
    float l = -1e30f;
    if (lane < KK) {
        int m = ent[idx];
        l = mask[idx] ? L[(w >> 7) * MM + m] : -1e25f;
    }
    float mx = l;
#pragma unroll
    for (int o = 8; o; o >>= 1) mx = fmaxf(mx, __shfl_xor_sync(0xffffffffu, mx, o));
    float e = expf(l - mx);
    float s = e;
#pragma unroll
    for (int o = 8; o; o >>= 1) s += __shfl_xor_sync(0xffffffffu, s, o);
    if (lane < KK) attn[idx] = e / s;
}

// ---------------------------------------------------------------------------
// Weighted pooling over K mentions -> entity reprs g_E [BE, H]
// ---------------------------------------------------------------------------
__global__ void __launch_bounds__(256)
pool_kernel(const float* __restrict__ attn, const int* __restrict__ ent,
            const float* __restrict__ mr, float* __restrict__ E)
{
    const int be = blockIdx.x;
    const int b = be >> 7;   // /E
    __shared__ float w[KK];
    __shared__ int rows[KK];
    if (threadIdx.x < KK) {
        w[threadIdx.x] = attn[be * KK + threadIdx.x];
        rows[threadIdx.x] = b * MM + ent[be * KK + threadIdx.x];
    }
    __syncthreads();
    for (int h = threadIdx.x; h < HH; h += 256) {
        float s = 0.f;
#pragma unroll
        for (int k = 0; k < KK; k++)
            s = fmaf(w[k], mr[(size_t)rows[k] * HH + h], s);
        E[(size_t)be * HH + h] = s;
    }
}

// ---------------------------------------------------------------------------
// Transpose relation_memory [R, RMS] -> RMt [RMS, R]
// ---------------------------------------------------------------------------
__global__ void __launch_bounds__(1024)
transpose_rm(const float* __restrict__ RM, float* __restrict__ RMt)
{
    __shared__ float t[32][33];
    const int r0 = blockIdx.y * 32;
    const int m0 = blockIdx.x * 32;
    t[threadIdx.y][threadIdx.x] = RM[(size_t)(r0 + threadIdx.y) * RMS + m0 + threadIdx.x];
    __syncthreads();
    RMt[(size_t)(m0 + threadIdx.y) * RR + r0 + threadIdx.x] = t[threadIdx.x][threadIdx.y];
}

// ---------------------------------------------------------------------------
// Column sums of RM: r[m] = sum_r RM[r, m]
// ---------------------------------------------------------------------------
__global__ void __launch_bounds__(128)
colsum_rm(const float* __restrict__ RM, float* __restrict__ r)
{
    const int m = blockIdx.x * 128 + threadIdx.x;   // 512 total
    float s = 0.f;
    for (int i = 0; i < RR; i++) s += RM[(size_t)i * RMS + m];
    r[m] = s;
}

// ---------------------------------------------------------------------------
extern "C" void kernel_launch(void* const* d_in, const int* in_sizes, int n_in,
                              void* d_out, int out_size)
{
    const float* mr   = (const float*)d_in[0];
    const int*   ent  = (const int*)  d_in[1];
    const int*   emask= (const int*)  d_in[2];
    const float* RM   = (const float*)d_in[3];
    const float* Wv   = (const float*)d_in[4];
    const float* bv   = (const float*)d_in[5];
    const float* Wu   = (const float*)d_in[6];
    const float* bu   = (const float*)d_in[7];
    const float* Wa   = (const float*)d_in[8];
    const float* ba   = (const float*)d_in[9];
    const float* Wr   = (const float*)d_in[10];
    const float* br   = (const float*)d_in[11];
    const float* Wo   = (const float*)d_in[12];
    const float* bo   = (const float*)d_in[13];
    float* out = (float*)d_out;

    float *P, *L, *attn, *E, *RMt, *Cg, *rv, *Teff, *G;
    cudaGetSymbolAddress((void**)&P,   g_P);
    cudaGetSymbolAddress((void**)&L,   g_L);
    cudaGetSymbolAddress((void**)&attn,g_attn);
    cudaGetSymbolAddress((void**)&E,   g_E);
    cudaGetSymbolAddress((void**)&RMt, g_RMt);
    cudaGetSymbolAddress((void**)&Cg,  g_C);
    cudaGetSymbolAddress((void**)&rv,  g_r);
    cudaGetSymbolAddress((void**)&Teff,g_Teff);
    cudaGetSymbolAddress((void**)&G,   g_G);

    // Allow >48KB dynamic smem (host-side attribute, not an allocation)
    cudaFuncSetAttribute(mmagemm<0>, cudaFuncAttributeMaxDynamicSharedMemorySize, MG_SMEM);
    cudaFuncSetAttribute(mmagemm<1>, cudaFuncAttributeMaxDynamicSharedMemorySize, MG_SMEM);
    cudaFuncSetAttribute(mmagemm<2>, cudaFuncAttributeMaxDynamicSharedMemorySize, MG_SMEM);
    cudaFuncSetAttribute(mmagemm<4>, cudaFuncAttributeMaxDynamicSharedMemorySize, MG_SMEM);

    // Side streams/events (host-side resources only; created once).
    static cudaStream_t s1 = nullptr, s2 = nullptr, s3 = nullptr;
    static cudaEvent_t eR = nullptr, e1 = nullptr, e2 = nullptr, e3 = nullptr;
    if (!s1) {
        cudaStreamCreateWithFlags(&s1, cudaStreamNonBlocking);
        cudaStreamCreateWithFlags(&s2, cudaStreamNonBlocking);
        cudaStreamCreateWithFlags(&s3, cudaStreamNonBlocking);
        cudaEventCreateWithFlags(&eR, cudaEventDisableTiming);
        cudaEventCreateWithFlags(&e1, cudaEventDisableTiming);
        cudaEventCreateWithFlags(&e2, cudaEventDisableTiming);
        cudaEventCreateWithFlags(&e3, cudaEventDisableTiming);
    }

    // fork
    cudaEventRecord(eR, 0);
    cudaStreamWaitEvent(s1, eR, 0);
    cudaStreamWaitEvent(s2, eR, 0);
    cudaStreamWaitEvent(s3, eR, 0);

    // --- branch A1 (s1): Pv = MR @ Wv^T -> P[:,0:256]  grid (4,16)=64 ---
    mmagemm<0><<<dim3(AA / TN, BM_TOT / TM), 256, MG_SMEM, s1>>>(
        mr, Wv, nullptr, nullptr, nullptr, P, HH, HH, 2 * AA, 0, HH);
    cudaEventRecord(e1, s1);

    // --- branch A2 (s2): Pu = MR @ Wu^T -> P[:,256:512]  grid (4,16)=64 ---
    mmagemm<0><<<dim3(AA / TN, BM_TOT / TM), 256, MG_SMEM, s2>>>(
        mr, Wu, nullptr, nullptr, nullptr, P + AA, HH, HH, 2 * AA, 0, HH);
    cudaEventRecord(e2, s2);

    // --- branch B (s3): effective output weight G via Gram matrix ---
    colsum_rm<<<RMS / 128, 128, 0, s3>>>(RM, rv);
    transpose_rm<<<dim3(RMS / 32, RR / 32), dim3(32, 32), 0, s3>>>(RM, RMt);
    // C = RMt @ RMt^T  [512,512,K=1024]  grid (8,4)=32
    mmagemm<0><<<dim3(RMS / TN, RMS / TM), 256, MG_SMEM, s3>>>(
        RMt, RMt, nullptr, nullptr, nullptr, Cg, RR, RR, RMS, 0, RR);
    // Teff = Wr @ C (C symmetric) + br·r^T  [1024,512,K=512]  grid (8,8)=64
    mmagemm<4><<<dim3(RMS / TN, HH / TM), 256, MG_SMEM, s3>>>(
        Wr, Cg, br, rv, nullptr, Teff, RMS, RMS, RMS, 0, RMS);
    // G = Wo2 @ Teff^T + Wo1  [1024,1024,K=512]  grid (16,8)=128
    mmagemm<2><<<dim3(HH / TN, HH / TM), 256, MG_SMEM, s3>>>(
        Wo + HH, Teff, nullptr, nullptr, Wo, G, ZW, RMS, HH, ZW, RMS);
    cudaEventRecord(e3, s3);

    // --- default stream: attention chain after Pv,Pu ---
    cudaStreamWaitEvent(0, e1, 0);
    cudaStreamWaitEvent(0, e2, 0);
    mil_logits<<<BM_TOT / 8, 256>>>(P, bv, bu, Wa, ba, L);
    softmax16<<<BE / 8, 256>>>(L, ent, emask, attn);
    pool_kernel<<<BE, 256>>>(attn, ent, mr, E);

    // join with branch B, then final GEMM
    cudaStreamWaitEvent(0, e3, 0);
    // out = E @ G^T + bo  [1024,1024,K=1024]  grid (16,8)=128
    mmagemm<1><<<dim3(HH / TN, BE / TM), 256, MG_SMEM>>>(
        E, G, bo, nullptr, nullptr, out, HH, HH, HH, 0, HH);

    (void)in_sizes; (void)n_in; (void)out_size;
}

// round 14
// speedup vs baseline: 1.9295x; 1.4076x over previous
#include <cuda_runtime.h>
#include <cuda_bf16.h>
#include <math.h>
#include <stdint.h>

// Problem constants
#define BB 8
#define MM 256
#define EE 128
#define KK 16
#define HH 1024
#define AA 256
#define RR 1024
#define RMS 512
#define BE (BB*EE)          // 1024
#define BM_TOT (BB*MM)      // 2048 unique mentions
#define ZW (HH + RMS)       // 1536

typedef __nv_bfloat16 bf16;

// fp32 scratch
__device__ float g_P[BM_TOT * 2 * AA];  // [2048, 512]
__device__ float g_L[BM_TOT];
__device__ float g_attn[BE * KK];
__device__ float g_r[RMS];
// bf16 hi/lo operand scratch
__device__ bf16 g_mr_hi[BM_TOT * HH],  g_mr_lo[BM_TOT * HH];
__device__ bf16 g_Wv_hi[AA * HH],      g_Wv_lo[AA * HH];
__device__ bf16 g_Wu_hi[AA * HH],      g_Wu_lo[AA * HH];
__device__ bf16 g_Wr_hi[HH * RMS],     g_Wr_lo[HH * RMS];
__device__ bf16 g_Wo_hi[HH * ZW],      g_Wo_lo[HH * ZW];
__device__ bf16 g_RMt_hi[RMS * RR],    g_RMt_lo[RMS * RR];
__device__ bf16 g_Cg_hi[RMS * RMS],    g_Cg_lo[RMS * RMS];
__device__ bf16 g_Tf_hi[HH * RMS],     g_Tf_lo[HH * RMS];
__device__ bf16 g_G_hi[HH * HH],       g_G_lo[HH * HH];
__device__ bf16 g_E_hi[BE * HH],       g_E_lo[BE * HH];

__device__ __forceinline__ uint32_t smem_to_u32(const void* p) {
    uint32_t a;
    asm("{ .reg .u64 t; cvta.to.shared.u64 t, %1; cvt.u32.u64 %0, t; }"
        : "=r"(a) : "l"(p));
    return a;
}

__device__ __forceinline__ void split4(float4 v, uint2& hi, uint2& lo) {
    bf16 hx = __float2bfloat16(v.x), hy = __float2bfloat16(v.y);
    bf16 hz = __float2bfloat16(v.z), hw = __float2bfloat16(v.w);
    bf16 lx = __float2bfloat16(v.x - __bfloat162float(hx));
    bf16 ly = __float2bfloat16(v.y - __bfloat162float(hy));
    bf16 lz = __float2bfloat16(v.z - __bfloat162float(hz));
    bf16 lw = __float2bfloat16(v.w - __bfloat162float(hw));
    hi.x = (uint32_t)__bfloat16_as_ushort(hx) | ((uint32_t)__bfloat16_as_ushort(hy) << 16);
    hi.y = (uint32_t)__bfloat16_as_ushort(hz) | ((uint32_t)__bfloat16_as_ushort(hw) << 16);
    lo.x = (uint32_t)__bfloat16_as_ushort(lx) | ((uint32_t)__bfloat16_as_ushort(ly) << 16);
    lo.y = (uint32_t)__bfloat16_as_ushort(lz) | ((uint32_t)__bfloat16_as_ushort(lw) << 16);
}

__device__ __forceinline__ void split1(float v, bf16& h, bf16& l) {
    h = __float2bfloat16(v);
    l = __float2bfloat16(v - __bfloat162float(h));
}

#define CP16(dst, src) \
    asm volatile("cp.async.ca.shared.global [%0], [%1], 16;" \
                 :: "r"(dst), "l"(src))
#define CP_COMMIT() asm volatile("cp.async.commit_group;" ::: "memory")
#define CP_WAIT0()  asm volatile("cp.async.wait_group 0;" ::: "memory")

// ---------------------------------------------------------------------------
// bf16x3-split HMMA GEMM over PRE-SPLIT operands, cp.async staging:
//   C[M,N] = A[M,K]·B[N,K]^T (+ epilogue), A/B given as bf16 hi/lo pairs.
// TM=128, TN=64, 256 threads (8 warps: 4 M x 2 N, warp 32x32), TKC=64,
// double-buffered smem with cp.async pipeline.
// MODE: 0=none, 1=col bias bias[n], 2=add Cadd, 4=bias[m]*bias2[n]
// SPLIT: 1 -> also write bf16 hi/lo of the result (Chi/Clo, stride ldc).
// The fp32 store is skipped when C == nullptr (SPLIT-only outputs).
// ---------------------------------------------------------------------------
#define TM 128
#define TN 64
#define TKC 64
#define KPAD 72
#define KPADB 144
#define OFF_AHI 0
#define OFF_ALO (TM * KPADB)                 // 18432
#define OFF_BHI (OFF_ALO + TM * KPADB)       // 36864
#define OFF_BLO (OFF_BHI + TN * KPADB)       // 46080
#define SBUF    (OFF_BLO + TN * KPADB)       // 55296
#define MG_SMEM (2 * SBUF)                   // 110592

template<int MODE, int SPLIT>
__global__ void __launch_bounds__(256)
mmagemm(const bf16* __restrict__ Ahi, const bf16* __restrict__ Alo,
        const bf16* __restrict__ Bhi, const bf16* __restrict__ Blo,
        const float* __restrict__ bias, const float* __restrict__ bias2,
        const float* __restrict__ Cadd, float* __restrict__ C,
        bf16* __restrict__ Chi, bf16* __restrict__ Clo,
        int lda, int ldb, int ldc, int ldadd, int Kdim)
{
    extern __shared__ char smem[];

    const int tid  = threadIdx.x;
    const int lane = tid & 31;
    const int wid  = tid >> 5;
    const int wm   = wid & 3;
    const int wn   = wid >> 2;
    const int bx = blockIdx.x, by = blockIdx.y;

    const uint32_t base_u = smem_to_u32(smem);

    float acc[2][4][4];
#pragma unroll
    for (int i = 0; i < 2; i++)
#pragma unroll
        for (int j = 0; j < 4; j++)
#pragma unroll
            for (int q = 0; q < 4; q++) acc[i][j][q] = 0.f;

    const bf16* AhiB = Ahi + (size_t)(by * TM) * lda;
    const bf16* AloB = Alo + (size_t)(by * TM) * lda;
    const bf16* BhiB = Bhi + (size_t)(bx * TN) * ldb;
    const bf16* BloB = Blo + (size_t)(bx * TN) * ldb;

    // ldmatrix lane addressing
    const int aRow = lane & 15;
    const int aKh  = (lane >> 4) * 8;
    const int bRow = lane & 7;
    const int bKh  = ((lane >> 3) & 1) * 8;

    // cp.async stage of one K-chunk into buffer bsel (pure 16B copies)
    auto stage = [&](int bsel, int k0) {
        const uint32_t bu = base_u + bsel * SBUF;
        // A: 128 rows x 8 segs = 1024 segs, 4 per thread
#pragma unroll
        for (int p = 0; p < 4; p++) {
            const int sid = p * 256 + tid;
            const int row = sid >> 3;
            const int seg = sid & 7;
            const size_t goff = (size_t)row * lda + k0 + seg * 8;
            const uint32_t doff = (uint32_t)row * KPADB + seg * 16;
            CP16(bu + OFF_AHI + doff, AhiB + goff);
            CP16(bu + OFF_ALO + doff, AloB + goff);
        }
        // B: 64 rows x 8 segs = 512 segs, 2 per thread
#pragma unroll
        for (int p = 0; p < 2; p++) {
            const int sid = p * 256 + tid;
            const int row = sid >> 3;
            const int seg = sid & 7;
            const size_t goff = (size_t)row * ldb + k0 + seg * 8;
            const uint32_t doff = (uint32_t)row * KPADB + seg * 16;
            CP16(bu + OFF_BHI + doff, BhiB + goff);
            CP16(bu + OFF_BLO + doff, BloB + goff);
        }
        CP_COMMIT();
    };

    const int nch = Kdim / TKC;
    stage(0, 0);
    int buf = 0;
    for (int ch = 0; ch < nch; ch++) {
        CP_WAIT0();
        __syncthreads();
        if (ch + 1 < nch) stage(buf ^ 1, (ch + 1) * TKC);

        const uint32_t bufu = base_u + buf * SBUF;
#pragma unroll
        for (int term = 0; term < 3; term++) {
            const uint32_t aB = bufu + ((term == 2) ? OFF_ALO : OFF_AHI);
            const uint32_t bB = bufu + ((term == 1) ? OFF_BLO : OFF_BHI);
#pragma unroll
            for (int ks = 0; ks < 4; ks++) {
                const int koff = ks * 16;
                uint32_t bf[4][2];
#pragma unroll
                for (int j = 0; j < 4; j++) {
                    const int bn = wn * 32 + j * 8;
                    const uint32_t addr = bB +
                        (uint32_t)(((bn + bRow) * KPAD + koff + bKh) * 2);
                    asm volatile(
                        "ldmatrix.sync.aligned.m8n8.x2.shared.b16 {%0,%1}, [%2];"
                        : "=r"(bf[j][0]), "=r"(bf[j][1]) : "r"(addr));
                }
                uint32_t af[2][4];
#pragma unroll
                for (int i = 0; i < 2; i++) {
                    const int bm = wm * 32 + i * 16;
                    const uint32_t addr = aB +
                        (uint32_t)(((bm + aRow) * KPAD + koff + aKh) * 2);
                    asm volatile(
                        "ldmatrix.sync.aligned.m8n8.x4.shared.b16 {%0,%1,%2,%3}, [%4];"
                        : "=r"(af[i][0]), "=r"(af[i][1]),
                          "=r"(af[i][2]), "=r"(af[i][3]) : "r"(addr));
                }
#pragma unroll
                for (int i = 0; i < 2; i++)
#pragma unroll
                    for (int j = 0; j < 4; j++) {
                        asm volatile(
                            "mma.sync.aligned.m16n8k16.row.col.f32.bf16.bf16.f32 "
                            "{%0,%1,%2,%3}, {%4,%5,%6,%7}, {%8,%9}, {%0,%1,%2,%3};"
                            : "+f"(acc[i][j][0]), "+f"(acc[i][j][1]),
                              "+f"(acc[i][j][2]), "+f"(acc[i][j][3])
                            : "r"(af[i][0]), "r"(af[i][1]),
                              "r"(af[i][2]), "r"(af[i][3]),
                              "r"(bf[j][0]), "r"(bf[j][1]));
                    }
            }
        }
        buf ^= 1;
    }

    // ---- epilogue ----
    const int mBase = by * TM + wm * 32;
    const int nBase = bx * TN + wn * 32;
    const int rOff = lane >> 2;
    const int cOff = (lane & 3) * 2;
    const bool wf32 = (C != nullptr);
#pragma unroll
    for (int i = 0; i < 2; i++) {
        const int r0 = mBase + i * 16 + rOff;
        const int r1 = r0 + 8;
        float rb0 = 0.f, rb1 = 0.f;
        if (MODE == 4) { rb0 = bias[r0]; rb1 = bias[r1]; }
#pragma unroll
        for (int j = 0; j < 4; j++) {
            const int cn = nBase + j * 8 + cOff;
            float2 v0 = make_float2(acc[i][j][0], acc[i][j][1]);
            float2 v1 = make_float2(acc[i][j][2], acc[i][j][3]);
            if (MODE == 1) {
                v0.x += bias[cn]; v0.y += bias[cn + 1];
                v1.x += bias[cn]; v1.y += bias[cn + 1];
            }
            if (MODE == 4) {
                v0.x += rb0 * bias2[cn]; v0.y += rb0 * bias2[cn + 1];
                v1.x += rb1 * bias2[cn]; v1.y += rb1 * bias2[cn + 1];
            }
            if (MODE == 2) {
                const float2 c0 = *(const float2*)(Cadd + (size_t)r0 * ldadd + cn);
                const float2 c1 = *(const float2*)(Cadd + (size_t)r1 * ldadd + cn);
                v0.x += c0.x; v0.y += c0.y;
                v1.x += c1.x; v1.y += c1.y;
            }
            if (wf32) {
                *(float2*)(C + (size_t)r0 * ldc + cn) = v0;
                *(float2*)(C + (size_t)r1 * ldc + cn) = v1;
            }
            if (SPLIT) {
                bf16 h0a, l0a, h0b, l0b, h1a, l1a, h1b, l1b;
                split1(v0.x, h0a, l0a); split1(v0.y, h0b, l0b);
                split1(v1.x, h1a, l1a); split1(v1.y, h1b, l1b);
                __nv_bfloat162 H0; H0.x = h0a; H0.y = h0b;
                __nv_bfloat162 L0; L0.x = l0a; L0.y = l0b;
                __nv_bfloat162 H1; H1.x = h1a; H1.y = h1b;
                __nv_bfloat162 L1; L1.x = l1a; L1.y = l1b;
                *(__nv_bfloat162*)(Chi + (size_t)r0 * ldc + cn) = H0;
                *(__nv_bfloat162*)(Clo + (size_t)r0 * ldc + cn) = L0;
                *(__nv_bfloat162*)(Chi + (size_t)r1 * ldc + cn) = H1;
                *(__nv_bfloat162*)(Clo + (size_t)r1 * ldc + cn) = L1;
            }
        }
    }
}

// ---------------------------------------------------------------------------
// Elementwise fp32 -> bf16 hi/lo split (vector-4)
// ---------------------------------------------------------------------------
__global__ void __launch_bounds__(256)
split_f32(const float* __restrict__ x, bf16* __restrict__ hi,
          bf16* __restrict__ lo, int n4)
{
    const int i = blockIdx.x * 256 + threadIdx.x;
    if (i >= n4) return;
    float4 v = ((const float4*)x)[i];
    uint2 h, l;
    split4(v, h, l);
    ((uint2*)hi)[i] = h;
    ((uint2*)lo)[i] = l;
}

// ---------------------------------------------------------------------------
// Per-mention MIL logit
// ---------------------------------------------------------------------------
__global__ void __launch_bounds__(256)
mil_logits(const float* __restrict__ P, const float* __restrict__ bv,
           const float* __restrict__ bu, const float* __restrict__ Wa,
           const float* __restrict__ ba, float* __restrict__ L)
{
    const int w = (blockIdx.x * 256 + threadIdx.x) >> 5;
    const int lane = threadIdx.x & 31;
    const float* p = P + (size_t)w * (2 * AA);
    float sum = 0.f;
#pragma unroll
    for (int j = 0; j < 8; j++) {
        int a = lane + j * 32;
        float v = tanhf(p[a] + bv[a]);
        float u = 1.f / (1.f + expf(-(p[AA + a] + bu[a])));
        sum += v * u * Wa[a];
    }
#pragma unroll
    for (int o = 16; o; o >>= 1) sum += __shfl_xor_sync(0xffffffffu, sum, o);
    if (lane == 0) L[w] = sum + ba[0];
}

// ---------------------------------------------------------------------------
// softmax over K=16 per (b,e)
// ---------------------------------------------------------------------------
__global__ void __launch_bounds__(256)
softmax16(const float* __restrict__ L, const int* __restrict__ ent,
          const int* __restrict__ mask, float* __restrict__ attn)
{
    const int w = (blockIdx.x * 256 + threadIdx.x) >> 5;
    const int lane = threadIdx.x & 31;
    const int idx = w * KK + (lane & 15);
    float l = -1e30f;
    if (lane < KK) {
        int m = ent[idx];
        l = mask[idx] ? L[(w >> 7) * MM + m] : -1e25f;
    }
    float mx = l;
#pragma unroll
    for (int o = 8; o; o >>= 1) mx = fmaxf(mx, __shfl_xor_sync(0xffffffffu, mx, o));
    float e = expf(l - mx);
    float s = e;
#pragma unroll
    for (int o = 8; o; o >>= 1) s += __shfl_xor_sync(0xffffffffu, s, o);
    if (lane < KK) attn[idx] = e / s;
}

// ---------------------------------------------------------------------------
// Weighted pooling -> entity reprs, emitted directly as bf16 hi/lo
// ---------------------------------------------------------------------------
__global__ void __launch_bounds__(256)
pool_kernel(const float* __restrict__ attn, const int* __restrict__ ent,
            const float* __restrict__ mr, bf16* __restrict__ Ehi,
            bf16* __restrict__ Elo)
{
    const int be = blockIdx.x;
    const int b = be >> 7;
    __shared__ float w[KK];
    __shared__ int rows[KK];
    if (threadIdx.x < KK) {
        w[threadIdx.x] = attn[be * KK + threadIdx.x];
        rows[threadIdx.x] = b * MM + ent[be * KK + threadIdx.x];
    }
    __syncthreads();
    for (int h = threadIdx.x; h < HH; h += 256) {
        float s = 0.f;
#pragma unroll
        for (int k = 0; k < KK; k++)
            s = fmaf(w[k], mr[(size_t)rows[k] * HH + h], s);
        bf16 hi, lo;
        split1(s, hi, lo);
        Ehi[(size_t)be * HH + h] = hi;
        Elo[(size_t)be * HH + h] = lo;
    }
}

// ---------------------------------------------------------------------------
// Transpose RM [R, RMS] -> RMt hi/lo [RMS, R]
// ---------------------------------------------------------------------------
__global__ void __launch_bounds__(1024)
transpose_rm(const float* __restrict__ RM, bf16* __restrict__ RMthi,
             bf16* __restrict__ RMtlo)
{
    __shared__ float t[32][33];
    const int r0 = blockIdx.y * 32;
    const int m0 = blockIdx.x * 32;
    t[threadIdx.y][threadIdx.x] = RM[(size_t)(r0 + threadIdx.y) * RMS + m0 + threadIdx.x];
    __syncthreads();
    float v = t[threadIdx.x][threadIdx.y];
    bf16 hi, lo;
    split1(v, hi, lo);
    const size_t o = (size_t)(m0 + threadIdx.y) * RR + r0 + threadIdx.x;
    RMthi[o] = hi;
    RMtlo[o] = lo;
}

// ---------------------------------------------------------------------------
// Column sums of RM
// ---------------------------------------------------------------------------
__global__ void __launch_bounds__(128)
colsum_rm(const float* __restrict__ RM, float* __restrict__ r)
{
    const int m = blockIdx.x * 128 + threadIdx.x;
    float s = 0.f;
    for (int i = 0; i < RR; i++) s += RM[(size_t)i * RMS + m];
    r[m] = s;
}

// ---------------------------------------------------------------------------
extern "C" void kernel_launch(void* const* d_in, const int* in_sizes, int n_in,
                              void* d_out, int out_size)
{
    const float* mr   = (const float*)d_in[0];
    const int*   ent  = (const int*)  d_in[1];
    const int*   emask= (const int*)  d_in[2];
    const float* RM   = (const float*)d_in[3];
    const float* Wv   = (const float*)d_in[4];
    const float* bv   = (const float*)d_in[5];
    const float* Wu   = (const float*)d_in[6];
    const float* bu   = (const float*)d_in[7];
    const float* Wa   = (const float*)d_in[8];
    const float* ba   = (const float*)d_in[9];
    const float* Wr   = (const float*)d_in[10];
    const float* br   = (const float*)d_in[11];
    const float* Wo   = (const float*)d_in[12];
    const float* bo   = (const float*)d_in[13];
    float* out = (float*)d_out;

    float *P, *L, *attn, *rv;
    cudaGetSymbolAddress((void**)&P,    g_P);
    cudaGetSymbolAddress((void**)&L,    g_L);
    cudaGetSymbolAddress((void**)&attn, g_attn);
    cudaGetSymbolAddress((void**)&rv,   g_r);
    bf16 *mrh, *mrl, *Wvh, *Wvl, *Wuh, *Wul, *Wrh, *Wrl, *Woh, *Wol;
    bf16 *RMth, *RMtl, *Cgh, *Cgl, *Tfh, *Tfl, *Gh, *Gl, *Eh, *El;
    cudaGetSymbolAddress((void**)&mrh, g_mr_hi);  cudaGetSymbolAddress((void**)&mrl, g_mr_lo);
    cudaGetSymbolAddress((void**)&Wvh, g_Wv_hi);  cudaGetSymbolAddress((void**)&Wvl, g_Wv_lo);
    cudaGetSymbolAddress((void**)&Wuh, g_Wu_hi);  cudaGetSymbolAddress((void**)&Wul, g_Wu_lo);
    cudaGetSymbolAddress((void**)&Wrh, g_Wr_hi);  cudaGetSymbolAddress((void**)&Wrl, g_Wr_lo);
    cudaGetSymbolAddress((void**)&Woh, g_Wo_hi);  cudaGetSymbolAddress((void**)&Wol, g_Wo_lo);
    cudaGetSymbolAddress((void**)&RMth, g_RMt_hi); cudaGetSymbolAddress((void**)&RMtl, g_RMt_lo);
    cudaGetSymbolAddress((void**)&Cgh, g_Cg_hi);  cudaGetSymbolAddress((void**)&Cgl, g_Cg_lo);
    cudaGetSymbolAddress((void**)&Tfh, g_Tf_hi);  cudaGetSymbolAddress((void**)&Tfl, g_Tf_lo);
    cudaGetSymbolAddress((void**)&Gh,  g_G_hi);   cudaGetSymbolAddress((void**)&Gl,  g_G_lo);
    cudaGetSymbolAddress((void**)&Eh,  g_E_hi);   cudaGetSymbolAddress((void**)&El,  g_E_lo);

    cudaFuncSetAttribute(mmagemm<0,0>, cudaFuncAttributeMaxDynamicSharedMemorySize, MG_SMEM);
    cudaFuncSetAttribute(mmagemm<0,1>, cudaFuncAttributeMaxDynamicSharedMemorySize, MG_SMEM);
    cudaFuncSetAttribute(mmagemm<4,1>, cudaFuncAttributeMaxDynamicSharedMemorySize, MG_SMEM);
    cudaFuncSetAttribute(mmagemm<2,1>, cudaFuncAttributeMaxDynamicSharedMemorySize, MG_SMEM);
    cudaFuncSetAttribute(mmagemm<1,0>, cudaFuncAttributeMaxDynamicSharedMemorySize, MG_SMEM);

    static cudaStream_t s1 = nullptr, s2 = nullptr, s3 = nullptr;
    static cudaEvent_t eR = nullptr, e1 = nullptr, e2 = nullptr, e3 = nullptr, eMr = nullptr;
    if (!s1) {
        cudaStreamCreateWithFlags(&s1, cudaStreamNonBlocking);
        cudaStreamCreateWithFlags(&s2, cudaStreamNonBlocking);
        cudaStreamCreateWithFlags(&s3, cudaStreamNonBlocking);
        cudaEventCreateWithFlags(&eR, cudaEventDisableTiming);
        cudaEventCreateWithFlags(&e1, cudaEventDisableTiming);
        cudaEventCreateWithFlags(&e2, cudaEventDisableTiming);
        cudaEventCreateWithFlags(&e3, cudaEventDisableTiming);
        cudaEventCreateWithFlags(&eMr, cudaEventDisableTiming);
    }

    // fork
    cudaEventRecord(eR, 0);
    cudaStreamWaitEvent(s1, eR, 0);
    cudaStreamWaitEvent(s2, eR, 0);
    cudaStreamWaitEvent(s3, eR, 0);

    // --- branch A1 (s1): split mr, Wv; Pv = MR @ Wv^T -> P[:,0:256] ---
    split_f32<<<(BM_TOT * HH / 4 + 255) / 256, 256, 0, s1>>>(mr, mrh, mrl, BM_TOT * HH / 4);
    cudaEventRecord(eMr, s1);
    split_f32<<<(AA * HH / 4 + 255) / 256, 256, 0, s1>>>(Wv, Wvh, Wvl, AA * HH / 4);
    mmagemm<0,0><<<dim3(AA / TN, BM_TOT / TM), 256, MG_SMEM, s1>>>(
        mrh, mrl, Wvh, Wvl, nullptr, nullptr, nullptr, P, nullptr, nullptr,
        HH, HH, 2 * AA, 0, HH);
    cudaEventRecord(e1, s1);

    // --- branch A2 (s2): split Wu; Pu = MR @ Wu^T -> P[:,256:512] ---
    split_f32<<<(AA * HH / 4 + 255) / 256, 256, 0, s2>>>(Wu, Wuh, Wul, AA * HH / 4);
    cudaStreamWaitEvent(s2, eMr, 0);
    mmagemm<0,0><<<dim3(AA / TN, BM_TOT / TM), 256, MG_SMEM, s2>>>(
        mrh, mrl, Wuh, Wul, nullptr, nullptr, nullptr, P + AA, nullptr, nullptr,
        HH, HH, 2 * AA, 0, HH);
    cudaEventRecord(e2, s2);

    // --- branch B (s3): effective output weight G via Gram matrix ---
    split_f32<<<(HH * RMS / 4 + 255) / 256, 256, 0, s3>>>(Wr, Wrh, Wrl, HH * RMS / 4);
    split_f32<<<(HH * ZW / 4 + 255) / 256, 256, 0, s3>>>(Wo, Woh, Wol, HH * ZW / 4);
    colsum_rm<<<RMS / 128, 128, 0, s3>>>(RM, rv);
    transpose_rm<<<dim3(RMS / 32, RR / 32), dim3(32, 32), 0, s3>>>(RM, RMth, RMtl);
    // Cg = RMt @ RMt^T  [512,512,K=1024] -> bf16 hi/lo only
    mmagemm<0,1><<<dim3(RMS / TN, RMS / TM), 256, MG_SMEM, s3>>>(
        RMth, RMtl, RMth, RMtl, nullptr, nullptr, nullptr,
        (float*)nullptr, Cgh, Cgl, RR, RR, RMS, 0, RR);
    // Teff = Wr @ Cg + br·r^T  [1024,512,K=512] -> bf16 hi/lo only
    mmagemm<4,1><<<dim3(RMS / TN, HH / TM), 256, MG_SMEM, s3>>>(
        Wrh, Wrl, Cgh, Cgl, br, rv, nullptr,
        (float*)nullptr, Tfh, Tfl, RMS, RMS, RMS, 0, RMS);
    // G = Wo2 @ Teff^T + Wo1  [1024,1024,K=512] -> bf16 hi/lo only
    mmagemm<2,1><<<dim3(HH / TN, HH / TM), 256, MG_SMEM, s3>>>(
        Woh + HH, Wol + HH, Tfh, Tfl, nullptr, nullptr, Wo,
        (float*)nullptr, Gh, Gl, ZW, RMS, HH, ZW, RMS);
    cudaEventRecord(e3, s3);

    // --- default stream: attention chain after Pv,Pu ---
    cudaStreamWaitEvent(0, e1, 0);
    cudaStreamWaitEvent(0, e2, 0);
    mil_logits<<<BM_TOT / 8, 256>>>(P, bv, bu, Wa, ba, L);
    softmax16<<<BE / 8, 256>>>(L, ent, emask, attn);
    pool_kernel<<<BE, 256>>>(attn, ent, mr, Eh, El);

    // join with branch B, then final GEMM
    cudaStreamWaitEvent(0, e3, 0);
    // out = E @ G^T + bo  [1024,1024,K=1024]
    mmagemm<1,0><<<dim3(HH / TN, BE / TM), 256, MG_SMEM>>>(
        Eh, El, Gh, Gl, bo, nullptr, nullptr, out, nullptr, nullptr,
        HH, HH, HH, 0, HH);

    (void)in_sizes; (void)n_in; (void)out_size;
}